// round 12
// baseline (speedup 1.0000x reference)
#include <cuda_runtime.h>

// Until operator: r[t] = max(min(1, psi[t]), min(phi[t], r[t+1])), r[T] = -inf.
// [B=1024, T=8192, C=2] fp32. (max,min)-semiring reverse scan, exact.
//
// Op f_t(r) = max(v_t, min(p_t, r)), v_t = min(1, psi[t]).
// Compose (f earlier in time): P = min(Pf,Pg); V = max(Vf, min(Pf,Vg)).
//
// R12: no data staging. Each thread owns 2 CONSECUTIVE float4s (4 timesteps,
// 32B) per iteration, loaded/stored directly. At 32B/thread each LDG/STG.128
// touches 8 lines -> ~1536 wf/SM-iter, under the ~2300-cyc DRAM time (R2's
// 64B/thread = 16 lines was over; R9/R11's smem staging fixed that but cost
// 12 smem ops/thread-iter -> L1 65.8% co-limiting). Also: cross-warp resolve
// done REDUNDANTLY by all warps (no warp-0 bubble, no warpin roundtrip),
// barriers 4->2 per iteration. 256 thr, 4 blocks/SM, prefetch-ahead.

#define B_ROWS 1024
#define T_LEN  8192
#define BLK    256
#define ROW_F4 (T_LEN * 2 / 4)     // 4096 float4 per row
#define ITERS  8
#define SEG_F4 (ROW_F4 / ITERS)    // 512 float4 per segment
#define NW     (BLK / 32)          // 8 warps

__device__ __forceinline__ float finf()  { return __int_as_float(0x7f800000); }
__device__ __forceinline__ float fninf() { return __int_as_float(0xff800000); }

__global__ void __launch_bounds__(BLK, 4)
until_kernel(const float4* __restrict__ phi,
             const float4* __restrict__ psi,
             float4* __restrict__ out)
{
    const int    row  = blockIdx.x;
    const size_t base = (size_t)row * ROW_F4;
    const int    tid  = threadIdx.x;
    const int    lane = tid & 31;
    const int    w    = tid >> 5;

    __shared__ float4 wop[NW];   // per-warp composed op (Px,Vx,Py,Vy)

    // Thread's element pair within a segment (time-contiguous 32B).
    const int e0 = 2 * tid, e1 = 2 * tid + 1;

    // Prologue: load the LAST (latest-time) segment directly.
    {
    }
    float4 cp0 = phi[base + (ITERS - 1) * SEG_F4 + e0];
    float4 cp1 = phi[base + (ITERS - 1) * SEG_F4 + e1];
    float4 cq0 = psi[base + (ITERS - 1) * SEG_F4 + e0];
    float4 cq1 = psi[base + (ITERS - 1) * SEG_F4 + e1];

    float cx = fninf(), cy = fninf();   // inter-iteration carry (every warp keeps
                                        // an identical copy — redundant resolve)

#pragma unroll 1
    for (int i = ITERS - 1; i >= 0; --i) {
        const size_t seg = base + (size_t)i * SEG_F4;

        // Prefetch next (earlier-time) segment; overlaps the scan chain below.
        float4 np0 = make_float4(0.f,0.f,0.f,0.f), np1 = np0, nq0 = np0, nq1 = np0;
        if (i > 0) {
            const size_t nseg = seg - SEG_F4;
            np0 = phi[nseg + e0];
            np1 = phi[nseg + e1];
            nq0 = psi[nseg + e0];
            nq1 = psi[nseg + e1];
        }

        // v = min(1, psi). Layout: .x=ch0@t, .y=ch1@t, .z=ch0@t+1, .w=ch1@t+1
        const float v0x = fminf(1.f, cq0.x), v0y = fminf(1.f, cq0.y);
        const float v0z = fminf(1.f, cq0.z), v0w = fminf(1.f, cq0.w);
        const float v1x = fminf(1.f, cq1.x), v1y = fminf(1.f, cq1.y);
        const float v1z = fminf(1.f, cq1.z), v1w = fminf(1.f, cq1.w);

        // Per-thread composed op over 4 timesteps, folded back-to-front.
        float Px = cp1.z, Vx = v1z;
        float Py = cp1.w, Vy = v1w;
        Vx = fmaxf(v1x, fminf(cp1.x, Vx)); Px = fminf(cp1.x, Px);
        Vy = fmaxf(v1y, fminf(cp1.y, Vy)); Py = fminf(cp1.y, Py);
        Vx = fmaxf(v0z, fminf(cp0.z, Vx)); Px = fminf(cp0.z, Px);
        Vy = fmaxf(v0w, fminf(cp0.w, Vy)); Py = fminf(cp0.w, Py);
        Vx = fmaxf(v0x, fminf(cp0.x, Vx)); Px = fminf(cp0.x, Px);
        Vy = fmaxf(v0y, fminf(cp0.y, Vy)); Py = fminf(cp0.y, Py);

        // Warp-level reverse inclusive scan (suffix compositions).
#pragma unroll
        for (int off = 1; off < 32; off <<= 1) {
            float Px2 = __shfl_down_sync(0xffffffffu, Px, off);
            float Vx2 = __shfl_down_sync(0xffffffffu, Vx, off);
            float Py2 = __shfl_down_sync(0xffffffffu, Py, off);
            float Vy2 = __shfl_down_sync(0xffffffffu, Vy, off);
            if (lane + off < 32) {
                Vx = fmaxf(Vx, fminf(Px, Vx2)); Px = fminf(Px, Px2);
                Vy = fmaxf(Vy, fminf(Py, Vy2)); Py = fminf(Py, Py2);
            }
        }
        // Exclusive within warp (suffix from lane+1); lane 31 = identity.
        float EPx = __shfl_down_sync(0xffffffffu, Px, 1);
        float EVx = __shfl_down_sync(0xffffffffu, Vx, 1);
        float EPy = __shfl_down_sync(0xffffffffu, Py, 1);
        float EVy = __shfl_down_sync(0xffffffffu, Vy, 1);
        if (lane == 31) { EPx = finf(); EVx = fninf(); EPy = finf(); EVy = fninf(); }

        // WAR guard: all warps finished reading wop from the previous iteration.
        __syncthreads();
        if (lane == 0) wop[w] = make_float4(Px, Vx, Py, Vy);
        __syncthreads();

        // Cross-warp resolve, REDUNDANT in every warp (no warp-0 bubble).
        float4 o = wop[lane & (NW - 1)];
        float WPx = o.x, WVx = o.y, WPy = o.z, WVy = o.w;
#pragma unroll
        for (int off = 1; off < NW; off <<= 1) {
            float P2 = __shfl_down_sync(0xffffffffu, WPx, off);
            float V2 = __shfl_down_sync(0xffffffffu, WVx, off);
            float P3 = __shfl_down_sync(0xffffffffu, WPy, off);
            float V3 = __shfl_down_sync(0xffffffffu, WVy, off);
            if (lane + off < NW) {
                WVx = fmaxf(WVx, fminf(WPx, V2)); WPx = fminf(WPx, P2);
                WVy = fmaxf(WVy, fminf(WPy, V3)); WPy = fminf(WPy, P3);
            }
        }
        // Entering op for THIS warp = inclusive suffix at position w+1
        // (identity for the last warp). Uniform shuffle source per warp.
        float XPx = __shfl_sync(0xffffffffu, WPx, (w + 1) & 31);
        float XVx = __shfl_sync(0xffffffffu, WVx, (w + 1) & 31);
        float XPy = __shfl_sync(0xffffffffu, WPy, (w + 1) & 31);
        float XVy = __shfl_sync(0xffffffffu, WVy, (w + 1) & 31);
        if (w == NW - 1) { XPx = finf(); XVx = fninf(); XPy = finf(); XVy = fninf(); }
        // Block aggregate = inclusive suffix at lane 0.
        float BPx = __shfl_sync(0xffffffffu, WPx, 0);
        float BVx = __shfl_sync(0xffffffffu, WVx, 0);
        float BPy = __shfl_sync(0xffffffffu, WPy, 0);
        float BVy = __shfl_sync(0xffffffffu, WVy, 0);

        // Entering value for this warp, then this thread.
        float winx = fmaxf(XVx, fminf(XPx, cx));
        float winy = fmaxf(XVy, fminf(XPy, cy));
        float rx = fmaxf(EVx, fminf(EPx, winx));
        float ry = fmaxf(EVy, fminf(EPy, winy));

        // Update carry (identical in every warp).
        cx = fmaxf(BVx, fminf(BPx, cx));
        cy = fmaxf(BVy, fminf(BPy, cy));

        // Sweep this thread's 4 timesteps; direct 32B/thread stores.
        float4 o1, o0;
        o1.z = fmaxf(v1z, fminf(cp1.z, rx));
        o1.w = fmaxf(v1w, fminf(cp1.w, ry));
        o1.x = fmaxf(v1x, fminf(cp1.x, o1.z));
        o1.y = fmaxf(v1y, fminf(cp1.y, o1.w));
        o0.z = fmaxf(v0z, fminf(cp0.z, o1.x));
        o0.w = fmaxf(v0w, fminf(cp0.w, o1.y));
        o0.x = fmaxf(v0x, fminf(cp0.x, o0.z));
        o0.y = fmaxf(v0y, fminf(cp0.y, o0.w));

        out[seg + e0] = o0;
        out[seg + e1] = o1;

        cp0 = np0; cp1 = np1; cq0 = nq0; cq1 = nq1;
    }
}

extern "C" void kernel_launch(void* const* d_in, const int* in_sizes, int n_in,
                              void* d_out, int out_size)
{
    const float4* phi = (const float4*)d_in[0];
    const float4* psi = (const float4*)d_in[1];
    float4*       o   = (float4*)d_out;
    until_kernel<<<B_ROWS, BLK>>>(phi, psi, o);
}

// round 13
// speedup vs baseline: 1.1061x; 1.1061x over previous
#include <cuda_runtime.h>

// Until operator: r[t] = max(min(1, psi[t]), min(phi[t], r[t+1])), r[T] = -inf.
// [B=1024, T=8192, C=2] fp32. (max,min)-semiring reverse scan, exact.
//
// Op f_t(r) = max(v_t, min(p_t, r)), v_t = min(1, psi[t]).
// Compose (f earlier in time): P = min(Pf,Pg); V = max(Vf, min(Pf,Vg)).
//
// R13: SINGLE-WAVE layout. BLK=128, 8 blocks/SM pinned -> 1184 slots >= 1024
// blocks: whole grid resident at once. R8-R12 all ran fractional waves
// (1.7-3.5) whose tails/transitions capped DRAM at ~62% while the HBM floor
// is ~24us. Also: 8 independent streams/SM (vs 4) to cover scan-chain
// latency, NW=4 -> 2-step cross-warp resolve, cheap 128-thread barriers.
// Inner structure = R12 (32B/thread time-contiguous direct LDG/STG,
// prefetch-ahead, redundant all-warp resolve).

#define B_ROWS 1024
#define T_LEN  8192
#define BLK    128
#define ROW_F4 (T_LEN * 2 / 4)     // 4096 float4 per row
#define ITERS  16
#define SEG_F4 (ROW_F4 / ITERS)    // 256 float4 per segment
#define NW     (BLK / 32)          // 4 warps

__device__ __forceinline__ float finf()  { return __int_as_float(0x7f800000); }
__device__ __forceinline__ float fninf() { return __int_as_float(0xff800000); }

__global__ void __launch_bounds__(BLK, 8)
until_kernel(const float4* __restrict__ phi,
             const float4* __restrict__ psi,
             float4* __restrict__ out)
{
    const int    row  = blockIdx.x;
    const size_t base = (size_t)row * ROW_F4;
    const int    tid  = threadIdx.x;
    const int    lane = tid & 31;
    const int    w    = tid >> 5;

    __shared__ float4 wop[NW];   // per-warp composed op (Px,Vx,Py,Vy)

    // Thread's element pair within a segment (time-contiguous 32B).
    const int e0 = 2 * tid, e1 = 2 * tid + 1;

    // Prologue: load the LAST (latest-time) segment directly.
    float4 cp0 = phi[base + (ITERS - 1) * SEG_F4 + e0];
    float4 cp1 = phi[base + (ITERS - 1) * SEG_F4 + e1];
    float4 cq0 = psi[base + (ITERS - 1) * SEG_F4 + e0];
    float4 cq1 = psi[base + (ITERS - 1) * SEG_F4 + e1];

    float cx = fninf(), cy = fninf();   // inter-iteration carry (identical copy
                                        // in every warp — redundant resolve)

#pragma unroll 1
    for (int i = ITERS - 1; i >= 0; --i) {
        const size_t seg = base + (size_t)i * SEG_F4;

        // Prefetch next (earlier-time) segment; overlaps the scan chain below.
        float4 np0 = make_float4(0.f,0.f,0.f,0.f), np1 = np0, nq0 = np0, nq1 = np0;
        if (i > 0) {
            const size_t nseg = seg - SEG_F4;
            np0 = phi[nseg + e0];
            np1 = phi[nseg + e1];
            nq0 = psi[nseg + e0];
            nq1 = psi[nseg + e1];
        }

        // v = min(1, psi). Layout: .x=ch0@t, .y=ch1@t, .z=ch0@t+1, .w=ch1@t+1
        const float v0x = fminf(1.f, cq0.x), v0y = fminf(1.f, cq0.y);
        const float v0z = fminf(1.f, cq0.z), v0w = fminf(1.f, cq0.w);
        const float v1x = fminf(1.f, cq1.x), v1y = fminf(1.f, cq1.y);
        const float v1z = fminf(1.f, cq1.z), v1w = fminf(1.f, cq1.w);

        // Per-thread composed op over 4 timesteps, folded back-to-front.
        float Px = cp1.z, Vx = v1z;
        float Py = cp1.w, Vy = v1w;
        Vx = fmaxf(v1x, fminf(cp1.x, Vx)); Px = fminf(cp1.x, Px);
        Vy = fmaxf(v1y, fminf(cp1.y, Vy)); Py = fminf(cp1.y, Py);
        Vx = fmaxf(v0z, fminf(cp0.z, Vx)); Px = fminf(cp0.z, Px);
        Vy = fmaxf(v0w, fminf(cp0.w, Vy)); Py = fminf(cp0.w, Py);
        Vx = fmaxf(v0x, fminf(cp0.x, Vx)); Px = fminf(cp0.x, Px);
        Vy = fmaxf(v0y, fminf(cp0.y, Vy)); Py = fminf(cp0.y, Py);

        // Warp-level reverse inclusive scan (suffix compositions).
#pragma unroll
        for (int off = 1; off < 32; off <<= 1) {
            float Px2 = __shfl_down_sync(0xffffffffu, Px, off);
            float Vx2 = __shfl_down_sync(0xffffffffu, Vx, off);
            float Py2 = __shfl_down_sync(0xffffffffu, Py, off);
            float Vy2 = __shfl_down_sync(0xffffffffu, Vy, off);
            if (lane + off < 32) {
                Vx = fmaxf(Vx, fminf(Px, Vx2)); Px = fminf(Px, Px2);
                Vy = fmaxf(Vy, fminf(Py, Vy2)); Py = fminf(Py, Py2);
            }
        }
        // Exclusive within warp (suffix from lane+1); lane 31 = identity.
        float EPx = __shfl_down_sync(0xffffffffu, Px, 1);
        float EVx = __shfl_down_sync(0xffffffffu, Vx, 1);
        float EPy = __shfl_down_sync(0xffffffffu, Py, 1);
        float EVy = __shfl_down_sync(0xffffffffu, Vy, 1);
        if (lane == 31) { EPx = finf(); EVx = fninf(); EPy = finf(); EVy = fninf(); }

        // WAR guard vs previous iteration's wop reads, then publish.
        __syncthreads();
        if (lane == 0) wop[w] = make_float4(Px, Vx, Py, Vy);
        __syncthreads();

        // Cross-warp resolve, redundant in every warp (NW=4 -> 2 steps).
        float4 o = wop[lane & (NW - 1)];
        float WPx = o.x, WVx = o.y, WPy = o.z, WVy = o.w;
#pragma unroll
        for (int off = 1; off < NW; off <<= 1) {
            float P2 = __shfl_down_sync(0xffffffffu, WPx, off);
            float V2 = __shfl_down_sync(0xffffffffu, WVx, off);
            float P3 = __shfl_down_sync(0xffffffffu, WPy, off);
            float V3 = __shfl_down_sync(0xffffffffu, WVy, off);
            if (lane + off < NW) {
                WVx = fmaxf(WVx, fminf(WPx, V2)); WPx = fminf(WPx, P2);
                WVy = fmaxf(WVy, fminf(WPy, V3)); WPy = fminf(WPy, P3);
            }
        }
        // Entering op for THIS warp = inclusive suffix at w+1 (identity for last).
        float XPx = __shfl_sync(0xffffffffu, WPx, (w + 1) & 31);
        float XVx = __shfl_sync(0xffffffffu, WVx, (w + 1) & 31);
        float XPy = __shfl_sync(0xffffffffu, WPy, (w + 1) & 31);
        float XVy = __shfl_sync(0xffffffffu, WVy, (w + 1) & 31);
        if (w == NW - 1) { XPx = finf(); XVx = fninf(); XPy = finf(); XVy = fninf(); }
        // Block aggregate = inclusive suffix at lane 0.
        float BPx = __shfl_sync(0xffffffffu, WPx, 0);
        float BVx = __shfl_sync(0xffffffffu, WVx, 0);
        float BPy = __shfl_sync(0xffffffffu, WPy, 0);
        float BVy = __shfl_sync(0xffffffffu, WVy, 0);

        // Entering value for this warp, then this thread.
        float winx = fmaxf(XVx, fminf(XPx, cx));
        float winy = fmaxf(XVy, fminf(XPy, cy));
        float rx = fmaxf(EVx, fminf(EPx, winx));
        float ry = fmaxf(EVy, fminf(EPy, winy));

        // Update carry (identical in every warp).
        cx = fmaxf(BVx, fminf(BPx, cx));
        cy = fmaxf(BVy, fminf(BPy, cy));

        // Sweep this thread's 4 timesteps; direct 32B/thread stores.
        float4 o1, o0;
        o1.z = fmaxf(v1z, fminf(cp1.z, rx));
        o1.w = fmaxf(v1w, fminf(cp1.w, ry));
        o1.x = fmaxf(v1x, fminf(cp1.x, o1.z));
        o1.y = fmaxf(v1y, fminf(cp1.y, o1.w));
        o0.z = fmaxf(v0z, fminf(cp0.z, o1.x));
        o0.w = fmaxf(v0w, fminf(cp0.w, o1.y));
        o0.x = fmaxf(v0x, fminf(cp0.x, o0.z));
        o0.y = fmaxf(v0y, fminf(cp0.y, o0.w));

        out[seg + e0] = o0;
        out[seg + e1] = o1;

        cp0 = np0; cp1 = np1; cq0 = nq0; cq1 = nq1;
    }
}

extern "C" void kernel_launch(void* const* d_in, const int* in_sizes, int n_in,
                              void* d_out, int out_size)
{
    const float4* phi = (const float4*)d_in[0];
    const float4* psi = (const float4*)d_in[1];
    float4*       o   = (float4*)d_out;
    until_kernel<<<B_ROWS, BLK>>>(phi, psi, o);
}